// round 8
// baseline (speedup 1.0000x reference)
#include <cuda_runtime.h>

#define NE 16
#define NK 4
#define NH 2048
#define NF 4096
#define NT 64
#define JA 12
#define ACH 6           // max j-chunks in stage A (ceil(64/12))
#define JB 8

typedef unsigned long long u64;

__device__ float g_act[(size_t)NE * NT * NF];   // 16.8 MB scratch
__device__ int   g_cnt[NE];
__device__ int   g_tok[NE * NT];
__device__ float g_rw [NE * NT];

__device__ __forceinline__ u64 pk2(float lo, float hi) {
    u64 r; asm("mov.b64 %0,{%1,%2};" : "=l"(r) : "f"(lo), "f"(hi)); return r;
}
__device__ __forceinline__ void upk2(u64 v, float &lo, float &hi) {
    asm("mov.b64 {%0,%1},%2;" : "=f"(lo), "=f"(hi) : "l"(v));
}
__device__ __forceinline__ void fma2(u64 &d, u64 a, u64 b) {
    asm("fma.rn.f32x2 %0,%1,%2,%0;" : "+l"(d) : "l"(a), "l"(b));
}
__device__ __forceinline__ u64 add2(u64 a, u64 b) {
    u64 r; asm("add.rn.f32x2 %0,%1,%2;" : "=l"(r) : "l"(a), "l"(b)); return r;
}
__device__ __forceinline__ void red4(float* p, float a, float b, float c, float d) {
    asm volatile("red.global.add.v4.f32 [%0], {%1,%2,%3,%4};"
                 :: "l"(p), "f"(a), "f"(b), "f"(c), "f"(d) : "memory");
}

// ---------------------------------------------------------------------------
// Setup: block 0 builds routing tables; all blocks zero the output.
// ---------------------------------------------------------------------------
__global__ void setup_kernel(const int* __restrict__ tope,
                             const float* __restrict__ topw,
                             float* __restrict__ out)
{
    const int gid = blockIdx.x * blockDim.x + threadIdx.x;
    float4 z = make_float4(0.f, 0.f, 0.f, 0.f);
    float4* o4 = (float4*)out;
    for (int i = gid; i < (NT * NH) / 4; i += gridDim.x * blockDim.x) o4[i] = z;

    if (blockIdx.x == 0) {
        __shared__ int   se[NT * NK];
        __shared__ float sw[NT * NK];
        const int tid = threadIdx.x;
        if (tid < NT * NK) { se[tid] = tope[tid]; sw[tid] = topw[tid]; }
        __syncthreads();
        if (tid < NE) {
            const int e = tid; int c = 0;
            for (int t = 0; t < NT; t++) {
                float r = 0.f; int hit = 0;
#pragma unroll
                for (int k = 0; k < NK; k++)
                    if (se[t * NK + k] == e) { r += sw[t * NK + k]; hit = 1; }
                if (hit) { g_tok[e * NT + c] = t; g_rw[e * NT + c] = r; c++; }
            }
            g_cnt[e] = c;
        }
    }
}

// ---------------------------------------------------------------------------
// Stage A: act[e][j][f] = rw * silu(x.w1_f) * (x.v1_f)
// Warp = 4 groups of 8 lanes; group g owns f-row f0+g of BOTH w1 and v1.
// All groups read the SAME 128B x chunk -> broadcast LDS.128 = 1 wavefront.
// Weight LDG.128 = 4 rows x 128B = 4 lines (coalescing unchanged).
// Acc: 2 u64 per j (h-paired). D=2 LDG ring. ~90 regs -> 2 CTAs/SM.
// ---------------------------------------------------------------------------
template<int JT>
__device__ __forceinline__ void stageA_body(
    const float* __restrict__ w1, const float* __restrict__ v1,
    const float* xs, const float* srw, int e, int fbase, int jbase, int J)
{
    const int tid = threadIdx.x, warp = tid >> 5, lane = tid & 31;
    const int grp = lane >> 3, sub = lane & 7;
    const int f = fbase + warp * 4 + grp;

    const ulonglong2* pw = (const ulonglong2*)(w1 + ((size_t)e * NF + f) * NH) + sub;
    const ulonglong2* pv = (const ulonglong2*)(v1 + ((size_t)e * NF + f) * NH) + sub;
    const ulonglong2* xp = (const ulonglong2*)xs + sub;

    u64 ga[JT], ua[JT];
#pragma unroll
    for (int j = 0; j < JT; j++) { ga[j] = 0ull; ua[j] = 0ull; }

    ulonglong2 rw_[2], rv_[2];
    rw_[0] = __ldg(pw);     rv_[0] = __ldg(pv);
    rw_[1] = __ldg(pw + 8); rv_[1] = __ldg(pv + 8);

#pragma unroll 2
    for (int c = 0; c < 64; c++) {
        const int sl = c & 1;
#pragma unroll
        for (int j = 0; j < JT; j++) {
            const ulonglong2 xv = xp[j * 512 + c * 8];   // broadcast LDS.128: 1 wf
            fma2(ga[j], rw_[sl].x, xv.x); fma2(ga[j], rw_[sl].y, xv.y);
            fma2(ua[j], rv_[sl].x, xv.x); fma2(ua[j], rv_[sl].y, xv.y);
        }
        if (c < 62) {
            rw_[sl] = __ldg(pw + (c + 2) * 8);
            rv_[sl] = __ldg(pv + (c + 2) * 8);
        }
    }

#pragma unroll
    for (int j = 0; j < JT; j++) {
        u64 gg = ga[j], uu = ua[j];
#pragma unroll
        for (int o = 4; o; o >>= 1) {                    // reduce within 8-lane group
            gg = add2(gg, __shfl_xor_sync(0xffffffffu, gg, o));
            uu = add2(uu, __shfl_xor_sync(0xffffffffu, uu, o));
        }
        if (sub == 0 && j < J) {
            float gl, gh, ul, uh;
            upk2(gg, gl, gh); upk2(uu, ul, uh);
            const float gv = gl + gh, uv = ul + uh;
            const float s = gv / (1.f + __expf(-gv));
            g_act[((size_t)(e * NT + jbase + j)) * NF + f] = s * uv * srw[j];
        }
    }
}

__global__ void __launch_bounds__(256, 2) stageA_kernel(
    const float* __restrict__ x, const float* __restrict__ w1, const float* __restrict__ v1)
{
    const int e = blockIdx.y;
    const int chunk = blockIdx.x % ACH, ftile = blockIdx.x / ACH;  // chunk fastest: L2 dedup
    const int jbase = chunk * JA;
    const int cnt = g_cnt[e];
    if (jbase >= cnt) return;
    const int J  = min(JA, cnt - jbase);
    const int Jp = ((J + 3) >> 2) << 2;

    extern __shared__ __align__(16) float xs[];
    __shared__ int   stok[JA];
    __shared__ float srw [JA];
    const int tid = threadIdx.x;
    if (tid < JA) {
        stok[tid] = (tid < J) ? g_tok[e * NT + jbase + tid] : 0;
        srw [tid] = (tid < J) ? g_rw [e * NT + jbase + tid] : 0.f;
    }
    __syncthreads();

    float4* xs4 = (float4*)xs;
    const float4* x4 = (const float4*)x;
    for (int idx = tid; idx < Jp * 512; idx += 256) {
        const int j = idx >> 9, q = idx & 511;
        xs4[idx] = (j < J) ? __ldg(x4 + (size_t)stok[j] * 512 + q)
                           : make_float4(0.f, 0.f, 0.f, 0.f);
    }
    __syncthreads();

    const int fbase = ftile * 32;
    switch ((J + 3) >> 2) {
        case 1:  stageA_body<4 >(w1, v1, xs, srw, e, fbase, jbase, J); break;
        case 2:  stageA_body<8 >(w1, v1, xs, srw, e, fbase, jbase, J); break;
        default: stageA_body<12>(w1, v1, xs, srw, e, fbase, jbase, J); break;
    }
}

// ---------------------------------------------------------------------------
// Stage B: out[t] += act[e][j] @ w2_e (rw already folded into act).
// Thread owns 8 h (4 u64 accs/j). Per 2-f step: 1 broadcast LDS.64 + 2 pk2
// feed 8 FFMA2 per j. D=2 ring on the 4 w2 streams. v4 red atomics epilogue.
// ---------------------------------------------------------------------------
template<int JT>
__device__ __forceinline__ void stageB_body(
    const float* __restrict__ w2, float* __restrict__ out,
    const float* sact, const int* stok, int e, int f0, int J)
{
    const int tid = threadIdx.x;                 // 256 threads, h = tid*8
    u64 A0[JT], A1[JT], A2[JT], A3[JT];
#pragma unroll
    for (int j = 0; j < JT; j++) { A0[j] = 0ull; A1[j] = 0ull; A2[j] = 0ull; A3[j] = 0ull; }

    const ulonglong2* wb = (const ulonglong2*)(w2 + ((size_t)e * NF + f0) * NH) + tid * 2;

    ulonglong2 R0[2], R1[2], R2[2], R3[2];       // [slot]: rows 2s (h0..3,h4..7) and 2s+1
#pragma unroll
    for (int s = 0; s < 2; s++) {
        R0[s] = __ldg(wb + (size_t)(2 * s    ) * 512);
        R1[s] = __ldg(wb + (size_t)(2 * s    ) * 512 + 1);
        R2[s] = __ldg(wb + (size_t)(2 * s + 1) * 512);
        R3[s] = __ldg(wb + (size_t)(2 * s + 1) * 512 + 1);
    }

#pragma unroll 2
    for (int s = 0; s < 128; s++) {
        const int sl = s & 1;
#pragma unroll
        for (int j = 0; j < JT; j++) {
            const float2 a2 = *(const float2*)(sact + j * 256 + 2 * s); // LDS.64 bcast
            const u64 dx = pk2(a2.x, a2.x);
            const u64 dy = pk2(a2.y, a2.y);
            fma2(A0[j], R0[sl].x, dx); fma2(A1[j], R0[sl].y, dx);
            fma2(A2[j], R1[sl].x, dx); fma2(A3[j], R1[sl].y, dx);
            fma2(A0[j], R2[sl].x, dy); fma2(A1[j], R2[sl].y, dy);
            fma2(A2[j], R3[sl].x, dy); fma2(A3[j], R3[sl].y, dy);
        }
        if (s < 126) {
            const int t = s + 2;
            R0[sl] = __ldg(wb + (size_t)(2 * t    ) * 512);
            R1[sl] = __ldg(wb + (size_t)(2 * t    ) * 512 + 1);
            R2[sl] = __ldg(wb + (size_t)(2 * t + 1) * 512);
            R3[sl] = __ldg(wb + (size_t)(2 * t + 1) * 512 + 1);
        }
    }

#pragma unroll
    for (int j = 0; j < JT; j++) {
        if (j < J) {
            float a0, a1, a2, a3, a4, a5, a6, a7;
            upk2(A0[j], a0, a1); upk2(A1[j], a2, a3);
            upk2(A2[j], a4, a5); upk2(A3[j], a6, a7);
            float* op = out + (size_t)stok[j] * NH + tid * 8;
            red4(op,     a0, a1, a2, a3);
            red4(op + 4, a4, a5, a6, a7);
        }
    }
}

__global__ void __launch_bounds__(256, 2) stageB_kernel(
    const float* __restrict__ w2, float* __restrict__ out)
{
    const int jc = blockIdx.x, e = blockIdx.y;            // jc fastest: L2 dedup on w2
    const int jbase = jc * JB;
    const int cnt = g_cnt[e];
    if (jbase >= cnt) return;
    const int J  = min(JB, cnt - jbase);
    const int Jp = ((J + 3) >> 2) << 2;
    const int f0 = blockIdx.z * 256;

    extern __shared__ __align__(16) float sact[];         // [JB][256] plain act
    __shared__ int stok[JB];
    const int tid = threadIdx.x;
    if (tid < JB) stok[tid] = (tid < J) ? g_tok[e * NT + jbase + tid] : 0;
    __syncthreads();

    for (int idx = tid; idx < Jp * 256; idx += 256) {
        const int j = idx >> 8, q = idx & 255;
        sact[idx] = (j < J)
            ? g_act[((size_t)(e * NT + jbase + j)) * NF + f0 + q] : 0.f;
    }
    __syncthreads();

    if (((J + 3) >> 2) == 1)
        stageB_body<4>(w2, out, sact, stok, e, f0, J);
    else
        stageB_body<8>(w2, out, sact, stok, e, f0, J);
}

// ---------------------------------------------------------------------------
extern "C" void kernel_launch(void* const* d_in, const int* in_sizes, int n_in,
                              void* d_out, int out_size)
{
    const float* x    = (const float*)d_in[0];
    const float* topw = (const float*)d_in[2];
    const int*   tope = (const int*)  d_in[3];
    const float* w1   = (const float*)d_in[4];
    const float* v1   = (const float*)d_in[5];
    const float* w2   = (const float*)d_in[6];
    float* out = (float*)d_out;

    cudaFuncSetAttribute(stageA_kernel, cudaFuncAttributeMaxDynamicSharedMemorySize, JA * NH * 4);
    cudaFuncSetAttribute(stageB_kernel, cudaFuncAttributeMaxDynamicSharedMemorySize, JB * 256 * 4);

    setup_kernel<<<64, 256>>>(tope, topw, out);
    stageA_kernel<<<dim3((NF / 32) * ACH, NE), 256, JA * NH * 4>>>(x, w1, v1);
    stageB_kernel<<<dim3(8, NE, 16), 256, JB * 256 * 4>>>(w2, out);
}